// round 12
// baseline (speedup 1.0000x reference)
#include <cuda_runtime.h>

// SSIM loss — R12: R10 inner structure made PERSISTENT (grid = 740 = 148 SMs
// x 5 resident blocks, each looping tiles) + cross-tile register accumulation
// (per-tile reduction removed), single final reduction via ticket.

typedef unsigned long long u64;

#define TX 64
#define TY 32
#define HALO 5
#define INW 74                      // TX + 2*HALO
#define VS 75                       // u64 stride (odd -> conflict-free LDS.64)
#define NTHREADS 256
#define IMG 512
#define TILES_X 8
#define TILES_Y 16
#define PLANES 48
#define NTILES (PLANES * TILES_Y * TILES_X)    // 6144
#define GRIDB 740                   // 148 SMs x 5 blocks, all resident
#define NPIX 12582912.0f

#define C1 1.0e-4f
#define C2 9.0e-4f

#define N_V (TY * VS)               // 2400 u64 per buffer

__device__ float g_partials[GRIDB];
__device__ unsigned g_ticket = 0;

// Normalized 1D Gaussian, window=11, sigma=1.5
__device__ __forceinline__ constexpr float Wt(int k) {
    constexpr float w[11] = {
        0.00102838f, 0.00759877f, 0.03600081f, 0.10936072f, 0.21300553f,
        0.26601169f,
        0.21300553f, 0.10936072f, 0.03600081f, 0.00759877f, 0.00102838f
    };
    return w[k];
}

// ---- f32x2 packed helpers ----
__device__ __forceinline__ u64 pk(float lo, float hi) {
    u64 r; asm("mov.b64 %0, {%1, %2};" : "=l"(r) : "f"(lo), "f"(hi)); return r;
}
__device__ __forceinline__ float2 upk(u64 v) {
    float2 r; asm("mov.b64 {%0, %1}, %2;" : "=f"(r.x), "=f"(r.y) : "l"(v)); return r;
}
__device__ __forceinline__ u64 fma2(u64 a, u64 b, u64 c) {
    u64 d; asm("fma.rn.f32x2 %0, %1, %2, %3;" : "=l"(d) : "l"(a), "l"(b), "l"(c)); return d;
}
__device__ __forceinline__ u64 mul2(u64 a, u64 b) {
    u64 d; asm("mul.rn.f32x2 %0, %1, %2;" : "=l"(d) : "l"(a), "l"(b)); return d;
}
__device__ __forceinline__ u64 wsel(const u64 (&w)[6], int k) {
    return w[k < 6 ? k : 10 - k];
}

// Vertical-blur task: WIN input rows -> NOUT output rows for column c.
template<int WIN, int NOUT>
__device__ __forceinline__ void vtask(
    const float* __restrict__ p_plane, const float* __restrict__ t_plane,
    bool interior, int gx, int gybase,
    u64* __restrict__ s_VA, u64* __restrict__ s_VB,
    int y0, int c, const u64 (&w2)[6])
{
    u64 a[WIN];
    if (interior) {
        const float* pp = p_plane + (long)gybase * IMG + gx;
        const float* tp = t_plane + (long)gybase * IMG + gx;
        #pragma unroll
        for (int i = 0; i < WIN; i++)
            a[i] = pk(__ldg(pp + i * IMG), __ldg(tp + i * IMG));
    } else {
        const bool xok = (unsigned)gx < IMG;
        #pragma unroll
        for (int i = 0; i < WIN; i++) {
            int gy = gybase + i;
            float pv = 0.0f, tv = 0.0f;
            if (xok & ((unsigned)gy < IMG)) {
                long o = (long)gy * IMG + gx;
                pv = __ldg(p_plane + o);
                tv = __ldg(t_plane + o);
            }
            a[i] = pk(pv, tv);
        }
    }
    #pragma unroll
    for (int j = 0; j < NOUT; j++) {
        u64 acc = mul2(wsel(w2, 0), a[j]);
        #pragma unroll
        for (int k = 1; k < 11; k++) acc = fma2(wsel(w2, k), a[j + k], acc);
        s_VA[(y0 + j) * VS + c] = acc;
    }
    #pragma unroll
    for (int i = 0; i < WIN; i++) {     // (p,t) -> (p^2+t^2, p*t)
        float2 v = upk(a[i]);
        a[i] = pk(fmaf(v.x, v.x, v.y * v.y), v.x * v.y);
    }
    #pragma unroll
    for (int j = 0; j < NOUT; j++) {
        u64 acc = mul2(wsel(w2, 0), a[j]);
        #pragma unroll
        for (int k = 1; k < 11; k++) acc = fma2(wsel(w2, k), a[j + k], acc);
        s_VB[(y0 + j) * VS + c] = acc;
    }
}

__global__ __launch_bounds__(NTHREADS, 5)
void ssim_tile_kernel(const float* __restrict__ pred,
                      const float* __restrict__ targ,
                      float* __restrict__ out) {
    __shared__ u64 s_VA[N_V];     // V-blurred (mu_p, mu_t)
    __shared__ u64 s_VB[N_V];     // V-blurred (E[p^2]+E[t^2], E[pt])
    __shared__ float s_warp[8];
    __shared__ int   s_last;

    const int tid = threadIdx.x;
    const int bid = blockIdx.x;

    u64 w2[6];
    #pragma unroll
    for (int k = 0; k < 6; k++) w2[k] = pk(Wt(k), Wt(k));

    float local = 0.0f;

    // ---- Persistent tile loop: fixed order, deterministic ----
    for (int tile = bid; tile < NTILES; tile += GRIDB) {
        const int plane = tile >> 7;            // tile / 128
        const int rem   = tile & 127;
        const int tyi   = rem >> 3;             // 0..15
        const int txi   = rem & 7;              // 0..7
        const int ox = txi * TX;
        const int oy = tyi * TY;
        const long plane_base = (long)plane * (IMG * IMG);
        const float* __restrict__ p_plane = pred + plane_base;
        const float* __restrict__ t_plane = targ + plane_base;

        const bool interior =
            (txi != 0) & (txi != TILES_X - 1) &
            (tyi != 0) & (tyi != TILES_Y - 1);

        // Phase 1: vertical blur. 296 tasks = 74 cols x 4 groups of 8 outputs.
        #pragma unroll 1
        for (int it = 0; it < 2; it++) {
            int task = tid + it * NTHREADS;
            if (task < INW * 4) {
                int c = task % INW;
                int g = task / INW;
                int gx = ox + c - HALO;
                int y0 = 8 * g;
                vtask<18, 8>(p_plane, t_plane, interior, gx,
                             oy + y0 - HALO, s_VA, s_VB, y0, c, w2);
            }
        }
        __syncthreads();

        // Phase 2: horizontal blur + SSIM. 512 tasks of 4 cols, 2 rounds.
        #pragma unroll
        for (int it = 0; it < 2; it++) {
            const int task = tid + it * NTHREADS;   // 0..511
            const int r = task & 31;
            const int grp = task >> 5;              // 0..15
            const int base = r * VS + 4 * grp;

            u64 amu[4];
            {
                u64 h[14];
                #pragma unroll
                for (int i = 0; i < 14; i++) h[i] = s_VA[base + i];
                #pragma unroll
                for (int j = 0; j < 4; j++) {
                    u64 acc = mul2(wsel(w2, 0), h[j]);
                    #pragma unroll
                    for (int k = 1; k < 11; k++) acc = fma2(wsel(w2, k), h[j + k], acc);
                    amu[j] = acc;
                }
            }
            u64 asb[4];
            {
                u64 h[14];
                #pragma unroll
                for (int i = 0; i < 14; i++) h[i] = s_VB[base + i];
                #pragma unroll
                for (int j = 0; j < 4; j++) {
                    u64 acc = mul2(wsel(w2, 0), h[j]);
                    #pragma unroll
                    for (int k = 1; k < 11; k++) acc = fma2(wsel(w2, k), h[j + k], acc);
                    asb[j] = acc;
                }
            }
            #pragma unroll
            for (int j = 0; j < 4; j++) {
                float2 mu = upk(amu[j]);
                float2 sb = upk(asb[j]);        // (E[p^2]+E[t^2], E[pt])
                float mu_p2 = mu.x * mu.x;
                float mu_t2 = mu.y * mu.y;
                float mu_pt = mu.x * mu.y;
                float num = (2.0f * mu_pt + C1) * (2.0f * (sb.y - mu_pt) + C2);
                float den = (mu_p2 + mu_t2 + C1) * ((sb.x - mu_p2 - mu_t2) + C2);
                local += __fdividef(num, den);
            }
        }
        __syncthreads();   // protect V-buffers before next tile's phase 1
    }

    // ---- Final block reduction (once per block) ----
    float v = local;
    #pragma unroll
    for (int off = 16; off; off >>= 1)
        v += __shfl_xor_sync(0xFFFFFFFFu, v, off);
    if ((tid & 31) == 0) s_warp[tid >> 5] = v;
    __syncthreads();
    if (tid < 8) {
        v = s_warp[tid];
        #pragma unroll
        for (int off = 4; off; off >>= 1)
            v += __shfl_xor_sync(0x000000FFu, v, off);
    }
    if (tid == 0) {
        g_partials[bid] = v;
        __threadfence();
        unsigned t = atomicInc(&g_ticket, GRIDB - 1);   // wraps -> self-reset
        s_last = (t == GRIDB - 1);
    }
    __syncthreads();

    // ---- Last block folds 740 partials (fixed order, deterministic) ----
    if (s_last) {
        float s = 0.0f;
        for (int i = tid; i < GRIDB; i += NTHREADS)
            s += __ldcg(&g_partials[i]);
        #pragma unroll
        for (int off = 16; off; off >>= 1)
            s += __shfl_xor_sync(0xFFFFFFFFu, s, off);
        if ((tid & 31) == 0) s_warp[tid >> 5] = s;
        __syncthreads();
        if (tid < 8) {
            s = s_warp[tid];
            #pragma unroll
            for (int off = 4; off; off >>= 1)
                s += __shfl_xor_sync(0x000000FFu, s, off);
            if (tid == 0) out[0] = 1.0f - s * (1.0f / NPIX);
        }
    }
}

extern "C" void kernel_launch(void* const* d_in, const int* in_sizes, int n_in,
                              void* d_out, int out_size) {
    const float* pred = (const float*)d_in[0];
    const float* targ = (const float*)d_in[1];
    float* out = (float*)d_out;

    ssim_tile_kernel<<<GRIDB, NTHREADS>>>(pred, targ, out);
}

// round 13
// speedup vs baseline: 1.1504x; 1.1504x over previous
#include <cuda_runtime.h>

// SSIM loss — R13: R10 pipeline with 128x16 tiles (x-halo 1.078x, same 5
// blocks/SM occupancy) and per-task 3-way boundary guards (zero-shortcut
// columns / fast unguarded / y-guarded), ticket-fused finish.

typedef unsigned long long u64;

#define TX 128
#define TY 16
#define HALO 5
#define INW 138                     // TX + 2*HALO
#define VS 139                      // u64 stride (odd; 139 mod 16 = 11 -> conflict-free)
#define NTHREADS 256
#define IMG 512
#define TILES_X 4
#define TILES_Y 32
#define PLANES 48
#define NBLOCKS (PLANES * TILES_Y * TILES_X)   // 6144
#define NPIX 12582912.0f

#define C1 1.0e-4f
#define C2 9.0e-4f

#define N_V (TY * VS)               // 2224 u64 per buffer

__device__ float g_partials[NBLOCKS];
__device__ unsigned g_ticket = 0;

// Normalized 1D Gaussian, window=11, sigma=1.5
__device__ __forceinline__ constexpr float Wt(int k) {
    constexpr float w[11] = {
        0.00102838f, 0.00759877f, 0.03600081f, 0.10936072f, 0.21300553f,
        0.26601169f,
        0.21300553f, 0.10936072f, 0.03600081f, 0.00759877f, 0.00102838f
    };
    return w[k];
}

// ---- f32x2 packed helpers ----
__device__ __forceinline__ u64 pk(float lo, float hi) {
    u64 r; asm("mov.b64 %0, {%1, %2};" : "=l"(r) : "f"(lo), "f"(hi)); return r;
}
__device__ __forceinline__ float2 upk(u64 v) {
    float2 r; asm("mov.b64 {%0, %1}, %2;" : "=f"(r.x), "=f"(r.y) : "l"(v)); return r;
}
__device__ __forceinline__ u64 fma2(u64 a, u64 b, u64 c) {
    u64 d; asm("fma.rn.f32x2 %0, %1, %2, %3;" : "=l"(d) : "l"(a), "l"(b), "l"(c)); return d;
}
__device__ __forceinline__ u64 mul2(u64 a, u64 b) {
    u64 d; asm("mul.rn.f32x2 %0, %1, %2;" : "=l"(d) : "l"(a), "l"(b)); return d;
}
__device__ __forceinline__ u64 wsel(const u64 (&w)[6], int k) {
    return w[k < 6 ? k : 10 - k];
}

// Vertical-blur task: WIN input rows -> NOUT output rows for column c.
// Per-task guards: x-out -> zeros; y-window inside -> fast; else y-guarded.
template<int WIN, int NOUT>
__device__ __forceinline__ void vtask(
    const float* __restrict__ p_plane, const float* __restrict__ t_plane,
    int gx, int gybase,
    u64* __restrict__ s_VA, u64* __restrict__ s_VB,
    int y0, int c, const u64 (&w2)[6])
{
    if ((unsigned)gx >= IMG) {          // whole column out of image -> zeros
        #pragma unroll
        for (int j = 0; j < NOUT; j++) {
            s_VA[(y0 + j) * VS + c] = 0ull;
            s_VB[(y0 + j) * VS + c] = 0ull;
        }
        return;
    }

    u64 a[WIN];
    if ((unsigned)gybase <= (IMG - WIN)) {   // fast path: window fully inside
        const float* pp = p_plane + (long)gybase * IMG + gx;
        const float* tp = t_plane + (long)gybase * IMG + gx;
        #pragma unroll
        for (int i = 0; i < WIN; i++)
            a[i] = pk(__ldg(pp + i * IMG), __ldg(tp + i * IMG));
    } else {
        #pragma unroll
        for (int i = 0; i < WIN; i++) {
            int gy = gybase + i;
            float pv = 0.0f, tv = 0.0f;
            if ((unsigned)gy < IMG) {
                long o = (long)gy * IMG + gx;
                pv = __ldg(p_plane + o);
                tv = __ldg(t_plane + o);
            }
            a[i] = pk(pv, tv);
        }
    }
    #pragma unroll
    for (int j = 0; j < NOUT; j++) {
        u64 acc = mul2(wsel(w2, 0), a[j]);
        #pragma unroll
        for (int k = 1; k < 11; k++) acc = fma2(wsel(w2, k), a[j + k], acc);
        s_VA[(y0 + j) * VS + c] = acc;
    }
    #pragma unroll
    for (int i = 0; i < WIN; i++) {     // (p,t) -> (p^2+t^2, p*t)
        float2 v = upk(a[i]);
        a[i] = pk(fmaf(v.x, v.x, v.y * v.y), v.x * v.y);
    }
    #pragma unroll
    for (int j = 0; j < NOUT; j++) {
        u64 acc = mul2(wsel(w2, 0), a[j]);
        #pragma unroll
        for (int k = 1; k < 11; k++) acc = fma2(wsel(w2, k), a[j + k], acc);
        s_VB[(y0 + j) * VS + c] = acc;
    }
}

__global__ __launch_bounds__(NTHREADS, 5)
void ssim_tile_kernel(const float* __restrict__ pred,
                      const float* __restrict__ targ,
                      float* __restrict__ out) {
    __shared__ u64 s_VA[N_V];     // V-blurred (mu_p, mu_t)
    __shared__ u64 s_VB[N_V];     // V-blurred (E[p^2]+E[t^2], E[pt])
    __shared__ float s_warp[8];
    __shared__ int   s_last;

    const int tid = threadIdx.x;
    const int ox = blockIdx.x * TX;
    const int oy = blockIdx.y * TY;
    const long plane_base = (long)blockIdx.z * (IMG * IMG);
    const float* __restrict__ p_plane = pred + plane_base;
    const float* __restrict__ t_plane = targ + plane_base;

    u64 w2[6];
    #pragma unroll
    for (int k = 0; k < 6; k++) w2[k] = pk(Wt(k), Wt(k));

    // ---- Phase 1: vertical blur from global.
    // 276 tasks = 138 halo-cols x 2 row-groups of 8 outputs (window 18).
    #pragma unroll 1
    for (int it = 0; it < 2; it++) {
        int task = tid + it * NTHREADS;
        if (task < INW * 2) {
            int c = task % INW;
            int g = task / INW;
            int gx = ox + c - HALO;
            int y0 = 8 * g;
            vtask<18, 8>(p_plane, t_plane, gx,
                         oy + y0 - HALO, s_VA, s_VB, y0, c, w2);
        }
    }
    __syncthreads();

    // ---- Phase 2: horizontal blur + SSIM. 512 tasks of 4 cols, 2 rounds.
    // r = task & 15 (16 rows), grp = task >> 4 (32 col-groups).
    float local = 0.0f;
    #pragma unroll
    for (int it = 0; it < 2; it++) {
        const int task = tid + it * NTHREADS;   // 0..511
        const int r = task & 15;
        const int grp = task >> 4;              // 0..31
        const int base = r * VS + 4 * grp;

        u64 amu[4];
        {
            u64 h[14];
            #pragma unroll
            for (int i = 0; i < 14; i++) h[i] = s_VA[base + i];
            #pragma unroll
            for (int j = 0; j < 4; j++) {
                u64 acc = mul2(wsel(w2, 0), h[j]);
                #pragma unroll
                for (int k = 1; k < 11; k++) acc = fma2(wsel(w2, k), h[j + k], acc);
                amu[j] = acc;
            }
        }
        u64 asb[4];
        {
            u64 h[14];
            #pragma unroll
            for (int i = 0; i < 14; i++) h[i] = s_VB[base + i];
            #pragma unroll
            for (int j = 0; j < 4; j++) {
                u64 acc = mul2(wsel(w2, 0), h[j]);
                #pragma unroll
                for (int k = 1; k < 11; k++) acc = fma2(wsel(w2, k), h[j + k], acc);
                asb[j] = acc;
            }
        }
        #pragma unroll
        for (int j = 0; j < 4; j++) {
            float2 mu = upk(amu[j]);
            float2 sb = upk(asb[j]);        // (E[p^2]+E[t^2], E[pt])
            float mu_p2 = mu.x * mu.x;
            float mu_t2 = mu.y * mu.y;
            float mu_pt = mu.x * mu.y;
            float num = (2.0f * mu_pt + C1) * (2.0f * (sb.y - mu_pt) + C2);
            float den = (mu_p2 + mu_t2 + C1) * ((sb.x - mu_p2 - mu_t2) + C2);
            local += __fdividef(num, den);
        }
    }

    // ---- Phase 3: block reduction ----
    float v = local;
    #pragma unroll
    for (int off = 16; off; off >>= 1)
        v += __shfl_xor_sync(0xFFFFFFFFu, v, off);
    if ((tid & 31) == 0) s_warp[tid >> 5] = v;
    __syncthreads();
    if (tid < 8) {
        v = s_warp[tid];
        #pragma unroll
        for (int off = 4; off; off >>= 1)
            v += __shfl_xor_sync(0x000000FFu, v, off);
    }
    if (tid == 0) {
        int bl = (blockIdx.z * TILES_Y + blockIdx.y) * TILES_X + blockIdx.x;
        g_partials[bl] = v;
        __threadfence();
        unsigned t = atomicInc(&g_ticket, NBLOCKS - 1);  // wraps -> self-reset
        s_last = (t == NBLOCKS - 1);
    }
    __syncthreads();

    // ---- Phase 4: last block folds partials (fixed order, deterministic) ----
    if (s_last) {
        float s = 0.0f;
        for (int i = tid; i < NBLOCKS; i += NTHREADS)
            s += __ldcg(&g_partials[i]);
        #pragma unroll
        for (int off = 16; off; off >>= 1)
            s += __shfl_xor_sync(0xFFFFFFFFu, s, off);
        if ((tid & 31) == 0) s_warp[tid >> 5] = s;
        __syncthreads();
        if (tid < 8) {
            s = s_warp[tid];
            #pragma unroll
            for (int off = 4; off; off >>= 1)
                s += __shfl_xor_sync(0x000000FFu, s, off);
            if (tid == 0) out[0] = 1.0f - s * (1.0f / NPIX);
        }
    }
}

extern "C" void kernel_launch(void* const* d_in, const int* in_sizes, int n_in,
                              void* d_out, int out_size) {
    const float* pred = (const float*)d_in[0];
    const float* targ = (const float*)d_in[1];
    float* out = (float*)d_out;

    dim3 grid(TILES_X, TILES_Y, PLANES);
    ssim_tile_kernel<<<grid, NTHREADS>>>(pred, targ, out);
}